// round 2
// baseline (speedup 1.0000x reference)
#include <cuda_runtime.h>

// out[t, e] = W[e, idx[t]] + b[e]
// X: int32 [B*S] (JAX demotes int64->int32; 65536 tokens)
// W: f32 [128, 500000], b: f32 [128], out: f32 [65536, 128]

#define EMBED 128
#define NUM_LABELS 500000LL
#define TOK_PER_BLK 8

__global__ __launch_bounds__(EMBED) void onehot_gather_kernel(
    const int* __restrict__ X,
    const float* __restrict__ W,
    const float* __restrict__ b,
    float* __restrict__ out)
{
    const int e = threadIdx.x;                       // embed row, 0..127
    const long long row_base = (long long)e * NUM_LABELS;
    const float bias = __ldg(b + e);

    const int t0 = blockIdx.x * TOK_PER_BLK;

    // 8 token indices (warp-broadcast loads; X is contiguous int32)
    int idx[TOK_PER_BLK];
#pragma unroll
    for (int j = 0; j < TOK_PER_BLK; j++)
        idx[j] = __ldg(X + t0 + j);

    // 8 independent scattered gathers -> MLP=8 per thread
    float v[TOK_PER_BLK];
#pragma unroll
    for (int j = 0; j < TOK_PER_BLK; j++)
        v[j] = __ldg(W + row_base + (long long)idx[j]);

    // coalesced stores: 128 contiguous floats per token
#pragma unroll
    for (int j = 0; j < TOK_PER_BLK; j++)
        out[(long long)(t0 + j) * EMBED + e] = v[j] + bias;
}

extern "C" void kernel_launch(void* const* d_in, const int* in_sizes, int n_in,
                              void* d_out, int out_size)
{
    const int*   X = (const int*)d_in[0];      // [B, S, 1] int32
    const float* W = (const float*)d_in[1];    // [128, 500000] f32
    const float* b = (const float*)d_in[2];    // [128] f32
    float*     out = (float*)d_out;            // [B, S, 128] f32

    const int n_tokens = in_sizes[0];          // 65536
    const int blocks = n_tokens / TOK_PER_BLK; // 8192

    onehot_gather_kernel<<<blocks, EMBED>>>(X, W, b, out);
}

// round 3
// speedup vs baseline: 1.4545x; 1.4545x over previous
#include <cuda_runtime.h>

// out[t, e] = W[e, idx[t]] + b[e]
// X: int32 [65536], W: f32 [128, 500000], b: f32 [128], out: f32 [65536, 128]
//
// Strategy: counting-sort tokens into 1024 index bins (bin = idx >> 9) so the
// gather walks W columns in near-sorted order -> same-sector duplicates hit
// L2/L1 and DRAM bursts are quasi-sequential instead of fully random.

#define EMBED       128
#define NUM_LABELS  500000LL
#define TOK_PER_BLK 8
#define NT          65536
#define NBINS       1024
#define BIN_SHIFT   9      // 500000 >> 9 = 976 < 1024

__device__ int g_hist[NBINS];
__device__ int g_cursor[NBINS];
__device__ int g_perm[NT];

__global__ void k_zero_hist()
{
    g_hist[threadIdx.x] = 0;
}

__global__ void k_hist(const int* __restrict__ X, int n)
{
    int t = blockIdx.x * blockDim.x + threadIdx.x;
    if (t < n) atomicAdd(&g_hist[X[t] >> BIN_SHIFT], 1);
}

// single block, NBINS threads: exclusive prefix sum of g_hist -> g_cursor
__global__ void k_scan()
{
    __shared__ int s[NBINS];
    int i = threadIdx.x;
    int my = g_hist[i];
    s[i] = my;
    __syncthreads();
    for (int off = 1; off < NBINS; off <<= 1) {
        int v = (i >= off) ? s[i - off] : 0;
        __syncthreads();
        s[i] += v;
        __syncthreads();
    }
    g_cursor[i] = s[i] - my;   // exclusive scan
}

__global__ void k_scatter(const int* __restrict__ X, int n)
{
    int t = blockIdx.x * blockDim.x + threadIdx.x;
    if (t < n) {
        int bin = X[t] >> BIN_SHIFT;
        int pos = atomicAdd(&g_cursor[bin], 1);
        g_perm[pos] = t;
    }
}

__global__ __launch_bounds__(EMBED) void k_gather(
    const int* __restrict__ X,
    const float* __restrict__ W,
    const float* __restrict__ b,
    float* __restrict__ out)
{
    const int e = threadIdx.x;                       // embed row, 0..127
    const long long row_base = (long long)e * NUM_LABELS;
    const float bias = __ldg(b + e);

    const int t0 = blockIdx.x * TOK_PER_BLK;

    // permuted token ids (warp-broadcast loads, contiguous)
    int tok[TOK_PER_BLK];
#pragma unroll
    for (int j = 0; j < TOK_PER_BLK; j++)
        tok[j] = g_perm[t0 + j];

    // indices for those tokens (near-sorted across the block)
    int idx[TOK_PER_BLK];
#pragma unroll
    for (int j = 0; j < TOK_PER_BLK; j++)
        idx[j] = __ldg(X + tok[j]);

    // 8 independent gathers; sorted order -> L2/L1 hits on shared sectors
    float v[TOK_PER_BLK];
#pragma unroll
    for (int j = 0; j < TOK_PER_BLK; j++)
        v[j] = __ldg(W + row_base + (long long)idx[j]);

    // full 512B contiguous store per token (permuted order, still line-aligned)
#pragma unroll
    for (int j = 0; j < TOK_PER_BLK; j++)
        out[(long long)tok[j] * EMBED + e] = v[j] + bias;
}

extern "C" void kernel_launch(void* const* d_in, const int* in_sizes, int n_in,
                              void* d_out, int out_size)
{
    const int*   X = (const int*)d_in[0];      // [B, S, 1] int32
    const float* W = (const float*)d_in[1];    // [128, 500000] f32
    const float* b = (const float*)d_in[2];    // [128] f32
    float*     out = (float*)d_out;            // [B, S, 128] f32

    const int n_tokens = in_sizes[0];          // 65536

    k_zero_hist<<<1, NBINS>>>();
    k_hist<<<(n_tokens + 255) / 256, 256>>>(X, n_tokens);
    k_scan<<<1, NBINS>>>();
    k_scatter<<<(n_tokens + 255) / 256, 256>>>(X, n_tokens);
    k_gather<<<n_tokens / TOK_PER_BLK, EMBED>>>(X, W, b, out);
}